// round 9
// baseline (speedup 1.0000x reference)
#include <cuda_runtime.h>
#include <cuda_bf16.h>

#define NCLS   1000
#define NCLS4  250          // NCLS / 4 float4 per row
#define MAXBLK 4096

// Scratch (no device allocation allowed -> __device__ globals)
__device__ float2       g_part[MAXBLK];  // per-block (sum_loss, sum_valid)
__device__ unsigned int g_ctr = 0;       // last-block ticket counter

// ---------------------------------------------------------------------------
// Fused kernel, multi-wave grid, ONE token per warp (best measured MLP shape):
// stream the 1000-float row compare-free, tiny L1 re-reads for the nested
// block sums, butterfly reduce, then per-block combine + last-block final
// reduction in fixed order (deterministic) writing the scalar in-kernel.
// ---------------------------------------------------------------------------
__global__ __launch_bounds__(256) void hll_fused(
    const float* __restrict__ inputs,
    const int*   __restrict__ target,   // int32 (JAX downcasts int64 w/o x64)
    float* __restrict__ out,
    int N, int nblk)
{
    const int warp = threadIdx.x >> 5;
    const int lane = threadIdx.x & 31;
    const int n = (blockIdx.x << 3) + warp;

    float lsum = 0.f, csum = 0.f;

    if (n < N) {
        const int ti = target[n];
        const bool valid = (ti != -100);
        const int t   = valid ? ti : 0;
        const int lo1 = (t / 10)  * 10;    // start of 10-block
        const int lo2 = (t / 100) * 100;   // start of 100-block

        const float*  __restrict__ rowf = inputs + (size_t)n * NCLS;
        const float4* __restrict__ row  = reinterpret_cast<const float4*>(rowf);

        // ---- Streaming pass: full row sum, compare-free ----
        float a0 = 0.f, a1 = 0.f, a2 = 0.f, a3 = 0.f;
        #pragma unroll
        for (int it = 0; it < 8; ++it) {
            const int idx = lane + (it << 5);
            if (idx < NCLS4) {
                const float4 v = row[idx];
                a0 += v.x; a1 += v.y; a2 += v.z; a3 += v.w;
            }
        }
        float s3 = (a0 + a1) + (a2 + a3);

        // ---- Targeted re-reads (L1 hits) ----
        float s2 = 0.f, s1 = 0.f;
        if (lane < 25) {                       // 100 floats = 25 float4
            const float4 v = row[(lo2 >> 2) + lane];
            s2 = (v.x + v.y) + (v.z + v.w);
        }
        if (lane < 10) s1 = rowf[lo1 + lane];  // 10 floats
        const float s0 = rowf[t];              // broadcast read (L1 hit)

        // ---- Warp butterfly reduce s1,s2,s3 ----
        #pragma unroll
        for (int off = 16; off; off >>= 1) {
            s1 += __shfl_xor_sync(0xffffffffu, s1, off);
            s2 += __shfl_xor_sync(0xffffffffu, s2, off);
            s3 += __shfl_xor_sync(0xffffffffu, s3, off);
        }

        if (lane == 0 && valid) {
            const float u0 = (s0 != 0.f) ? -logf(s0 / s1) : 0.f;
            const float u1 = (s1 != 0.f) ? -logf(s1 / s2) : 0.f;
            const float u2 = (s2 != 0.f) ? -logf(s2 / s3) : 0.f;
            lsum = u0 + 0.60653065971263342f * u1   // exp(-0.5)
                      + 0.36787944117144233f * u2;  // exp(-1.0)
            csum = 1.f;
        }
    }

    // ---- Per-block combine of the 8 warp accumulators ----
    __shared__ float2 sacc[8];
    __shared__ bool   s_last;
    if (lane == 0) sacc[warp] = make_float2(lsum, csum);
    __syncthreads();
    if (threadIdx.x == 0) {
        float L = 0.f, C = 0.f;
        #pragma unroll
        for (int w = 0; w < 8; ++w) { L += sacc[w].x; C += sacc[w].y; }
        g_part[blockIdx.x] = make_float2(L, C);
        __threadfence();
        const unsigned int ticket = atomicAdd(&g_ctr, 1u);
        s_last = (ticket == (unsigned)(nblk - 1));
    }
    __syncthreads();

    // ---- Last block: reduce the L2-resident partials in fixed order ----
    if (s_last) {
        float l = 0.f, c = 0.f;
        for (int i = threadIdx.x; i < nblk; i += 256) {
            const float2 v = g_part[i];
            l += v.x;
            c += v.y;
        }
        #pragma unroll
        for (int off = 16; off; off >>= 1) {
            l += __shfl_xor_sync(0xffffffffu, l, off);
            c += __shfl_xor_sync(0xffffffffu, c, off);
        }
        __shared__ float sl[8], sc[8];
        if (lane == 0) { sl[warp] = l; sc[warp] = c; }
        __syncthreads();
        if (threadIdx.x == 0) {
            float L = 0.f, C = 0.f;
            #pragma unroll
            for (int w = 0; w < 8; ++w) { L += sl[w]; C += sc[w]; }
            out[0] = L / fmaxf(C, 1.0f);
            g_ctr = 0;   // reset for next graph replay (deterministic)
        }
    }
}

// ---------------------------------------------------------------------------
// Inputs (metadata order): inputs f32 [N,1000], target i32 [N],
//                          onehot_num, onehot_den, weights (unused)
// ---------------------------------------------------------------------------
extern "C" void kernel_launch(void* const* d_in, const int* in_sizes, int n_in,
                              void* d_out, int out_size)
{
    const float* inputs = (const float*)d_in[0];
    const int*   target = (const int*)d_in[1];
    float*       out    = (float*)d_out;

    const int N = in_sizes[1];
    int nblk = (N + 7) / 8;                  // 4096 for N=32768 (1 tok/warp)
    if (nblk > MAXBLK) nblk = MAXBLK;        // N fixed at 32768; safety

    hll_fused<<<nblk, 256>>>(inputs, target, out, N, nblk);
}

// round 11
// speedup vs baseline: 1.1874x; 1.1874x over previous
#include <cuda_runtime.h>
#include <cuda_bf16.h>

#define NCLS   1000
#define NCLS4  250          // NCLS / 4 float4 per row
#define MAXBLK 4096

// Scratch (no device allocation allowed -> __device__ globals)
__device__ float2       g_part[MAXBLK];  // per-block (sum_loss, sum_valid)
__device__ unsigned int g_ctr = 0;       // last-block ticket counter

// Release-ordered ticket increment: guarantees prior .cg stores are visible
// in L2 before the increment lands. No MEMBAR / CCTL.IVALL emitted.
__device__ __forceinline__ unsigned int ticket_inc_release(unsigned int* p)
{
    unsigned int old;
    asm volatile("atom.add.release.gpu.global.u32 %0, [%1], 1;"
                 : "=r"(old) : "l"(p) : "memory");
    return old;
}

// ---------------------------------------------------------------------------
// Fused kernel, multi-wave grid, ONE token per warp (best measured MLP shape).
// Fence-free last-block reduction: partials via st.cg / ld.cg (L2-coherent),
// release atomic ticket. Fixed summation order -> deterministic result.
// ---------------------------------------------------------------------------
__global__ __launch_bounds__(256) void hll_fused(
    const float* __restrict__ inputs,
    const int*   __restrict__ target,   // int32 (JAX downcasts int64 w/o x64)
    float* __restrict__ out,
    int N, int nblk)
{
    const int warp = threadIdx.x >> 5;
    const int lane = threadIdx.x & 31;
    const int n = (blockIdx.x << 3) + warp;

    float lsum = 0.f, csum = 0.f;

    if (n < N) {
        const int ti = target[n];
        const bool valid = (ti != -100);
        const int t   = valid ? ti : 0;
        const int lo1 = (t / 10)  * 10;    // start of 10-block
        const int lo2 = (t / 100) * 100;   // start of 100-block

        const float*  __restrict__ rowf = inputs + (size_t)n * NCLS;
        const float4* __restrict__ row  = reinterpret_cast<const float4*>(rowf);

        // ---- Streaming pass: full row sum, compare-free ----
        float a0 = 0.f, a1 = 0.f, a2 = 0.f, a3 = 0.f;
        #pragma unroll
        for (int it = 0; it < 8; ++it) {
            const int idx = lane + (it << 5);
            if (idx < NCLS4) {
                const float4 v = row[idx];
                a0 += v.x; a1 += v.y; a2 += v.z; a3 += v.w;
            }
        }
        float s3 = (a0 + a1) + (a2 + a3);

        // ---- Targeted re-reads (L1 hits) ----
        float s2 = 0.f, s1 = 0.f;
        if (lane < 25) {                       // 100 floats = 25 float4
            const float4 v = row[(lo2 >> 2) + lane];
            s2 = (v.x + v.y) + (v.z + v.w);
        }
        if (lane < 10) s1 = rowf[lo1 + lane];  // 10 floats
        const float s0 = rowf[t];              // broadcast read (L1 hit)

        // ---- Warp butterfly reduce s1,s2,s3 ----
        #pragma unroll
        for (int off = 16; off; off >>= 1) {
            s1 += __shfl_xor_sync(0xffffffffu, s1, off);
            s2 += __shfl_xor_sync(0xffffffffu, s2, off);
            s3 += __shfl_xor_sync(0xffffffffu, s3, off);
        }

        if (lane == 0 && valid) {
            const float u0 = (s0 != 0.f) ? -logf(s0 / s1) : 0.f;
            const float u1 = (s1 != 0.f) ? -logf(s1 / s2) : 0.f;
            const float u2 = (s2 != 0.f) ? -logf(s2 / s3) : 0.f;
            lsum = u0 + 0.60653065971263342f * u1   // exp(-0.5)
                      + 0.36787944117144233f * u2;  // exp(-1.0)
            csum = 1.f;
        }
    }

    // ---- Per-block combine of the 8 warp accumulators ----
    __shared__ float2 sacc[8];
    __shared__ bool   s_last;
    if (lane == 0) sacc[warp] = make_float2(lsum, csum);
    __syncthreads();
    if (threadIdx.x == 0) {
        float L = 0.f, C = 0.f;
        #pragma unroll
        for (int w = 0; w < 8; ++w) { L += sacc[w].x; C += sacc[w].y; }
        __stcg(&g_part[blockIdx.x], make_float2(L, C));   // L2-direct store
        const unsigned int ticket = ticket_inc_release(&g_ctr);
        s_last = (ticket == (unsigned)(nblk - 1));
    }
    __syncthreads();

    // ---- Last block: reduce the L2-resident partials in fixed order ----
    if (s_last) {
        float l = 0.f, c = 0.f;
        for (int i = threadIdx.x; i < nblk; i += 256) {
            const float2 v = __ldcg(&g_part[i]);          // L2-direct load
            l += v.x;
            c += v.y;
        }
        #pragma unroll
        for (int off = 16; off; off >>= 1) {
            l += __shfl_xor_sync(0xffffffffu, l, off);
            c += __shfl_xor_sync(0xffffffffu, c, off);
        }
        __shared__ float sl[8], sc[8];
        if (lane == 0) { sl[warp] = l; sc[warp] = c; }
        __syncthreads();
        if (threadIdx.x == 0) {
            float L = 0.f, C = 0.f;
            #pragma unroll
            for (int w = 0; w < 8; ++w) { L += sl[w]; C += sc[w]; }
            out[0] = L / fmaxf(C, 1.0f);
            __stcg(&g_ctr, 0u);   // reset for next graph replay
        }
    }
}

// ---------------------------------------------------------------------------
// Inputs (metadata order): inputs f32 [N,1000], target i32 [N],
//                          onehot_num, onehot_den, weights (unused)
// ---------------------------------------------------------------------------
extern "C" void kernel_launch(void* const* d_in, const int* in_sizes, int n_in,
                              void* d_out, int out_size)
{
    const float* inputs = (const float*)d_in[0];
    const int*   target = (const int*)d_in[1];
    float*       out    = (float*)d_out;

    const int N = in_sizes[1];
    int nblk = (N + 7) / 8;                  // 4096 for N=32768 (1 tok/warp)
    if (nblk > MAXBLK) nblk = MAXBLK;        // N fixed at 32768; safety

    hll_fused<<<nblk, 256>>>(inputs, target, out, N, nblk);
}

// round 12
// speedup vs baseline: 1.2993x; 1.0943x over previous
#include <cuda_runtime.h>
#include <cuda_bf16.h>

#define NCLS   1000
#define NCLS4  250          // NCLS / 4 float4 per row

// Scratch (no device allocation allowed -> __device__ globals)
// Fixed-point Q32 accumulators: integer atomics commute -> bit-deterministic.
__device__ unsigned long long g_lsum = 0;   // sum(loss) * 2^32
__device__ unsigned int       g_cnt  = 0;   // valid-token count
__device__ unsigned int       g_ctr  = 0;   // finished-block ticket

// Fire-and-forget reductions (no return value -> no latency wait)
__device__ __forceinline__ void red_add_u64(unsigned long long* p, unsigned long long v)
{
    asm volatile("red.relaxed.gpu.global.add.u64 [%0], %1;" :: "l"(p), "l"(v) : "memory");
}
__device__ __forceinline__ void red_add_u32(unsigned int* p, unsigned int v)
{
    asm volatile("red.relaxed.gpu.global.add.u32 [%0], %1;" :: "l"(p), "r"(v) : "memory");
}
// Release prior REDs, acquire for the final reads.
__device__ __forceinline__ unsigned int ticket_acq_rel(unsigned int* p)
{
    unsigned int old;
    asm volatile("atom.acq_rel.gpu.global.add.u32 %0, [%1], 1;"
                 : "=r"(old) : "l"(p) : "memory");
    return old;
}
__device__ __forceinline__ unsigned long long ld_acq_u64(const unsigned long long* p)
{
    unsigned long long v;
    asm volatile("ld.acquire.gpu.global.u64 %0, [%1];" : "=l"(v) : "l"(p) : "memory");
    return v;
}
__device__ __forceinline__ unsigned int ld_acq_u32(const unsigned int* p)
{
    unsigned int v;
    asm volatile("ld.acquire.gpu.global.u32 %0, [%1];" : "=r"(v) : "l"(p) : "memory");
    return v;
}

// ---------------------------------------------------------------------------
// Single fused kernel. Main body identical to the best measured shape
// (1 token/warp, grid 4096, compare-free stream + L1 re-reads + butterfly).
// Epilogue: thread 0 fires 2 non-returning REDs + 1 ticket; no block-wide
// wait. The globally-last thread finalizes the scalar and resets state.
// ---------------------------------------------------------------------------
__global__ __launch_bounds__(256) void hll_fused(
    const float* __restrict__ inputs,
    const int*   __restrict__ target,   // int32 (JAX downcasts int64 w/o x64)
    float* __restrict__ out,
    int N, int nblk)
{
    const int warp = threadIdx.x >> 5;
    const int lane = threadIdx.x & 31;
    const int n = (blockIdx.x << 3) + warp;

    float lsum = 0.f, csum = 0.f;

    if (n < N) {
        const int ti = target[n];
        const bool valid = (ti != -100);
        const int t   = valid ? ti : 0;
        const int lo1 = (t / 10)  * 10;    // start of 10-block
        const int lo2 = (t / 100) * 100;   // start of 100-block

        const float*  __restrict__ rowf = inputs + (size_t)n * NCLS;
        const float4* __restrict__ row  = reinterpret_cast<const float4*>(rowf);

        // ---- Streaming pass: full row sum, compare-free ----
        float a0 = 0.f, a1 = 0.f, a2 = 0.f, a3 = 0.f;
        #pragma unroll
        for (int it = 0; it < 8; ++it) {
            const int idx = lane + (it << 5);
            if (idx < NCLS4) {
                const float4 v = row[idx];
                a0 += v.x; a1 += v.y; a2 += v.z; a3 += v.w;
            }
        }
        float s3 = (a0 + a1) + (a2 + a3);

        // ---- Targeted re-reads (L1 hits) ----
        float s2 = 0.f, s1 = 0.f;
        if (lane < 25) {                       // 100 floats = 25 float4
            const float4 v = row[(lo2 >> 2) + lane];
            s2 = (v.x + v.y) + (v.z + v.w);
        }
        if (lane < 10) s1 = rowf[lo1 + lane];  // 10 floats
        const float s0 = rowf[t];              // broadcast read (L1 hit)

        // ---- Warp butterfly reduce s1,s2,s3 ----
        #pragma unroll
        for (int off = 16; off; off >>= 1) {
            s1 += __shfl_xor_sync(0xffffffffu, s1, off);
            s2 += __shfl_xor_sync(0xffffffffu, s2, off);
            s3 += __shfl_xor_sync(0xffffffffu, s3, off);
        }

        if (lane == 0 && valid) {
            const float u0 = (s0 != 0.f) ? -logf(s0 / s1) : 0.f;
            const float u1 = (s1 != 0.f) ? -logf(s1 / s2) : 0.f;
            const float u2 = (s2 != 0.f) ? -logf(s2 / s3) : 0.f;
            lsum = u0 + 0.60653065971263342f * u1   // exp(-0.5)
                      + 0.36787944117144233f * u2;  // exp(-1.0)
            csum = 1.f;
        }
    }

    // ---- Per-block combine (one syncthreads; no post-atomic wait) ----
    __shared__ float2 sacc[8];
    if (lane == 0) sacc[warp] = make_float2(lsum, csum);
    __syncthreads();

    if (threadIdx.x == 0) {
        float L = 0.f, C = 0.f;
        #pragma unroll
        for (int w = 0; w < 8; ++w) { L += sacc[w].x; C += sacc[w].y; }

        // Exact fixed-point conversion: L has 24-bit mantissa, L*2^32 < 2^53.
        const unsigned long long fx =
            (unsigned long long)__double2ll_rn((double)L * 4294967296.0);
        red_add_u64(&g_lsum, fx);                 // fire-and-forget
        red_add_u32(&g_cnt, (unsigned int)C);     // fire-and-forget

        const unsigned int ticket = ticket_acq_rel(&g_ctr);
        if (ticket == (unsigned)(nblk - 1)) {
            // Globally last thread: all REDs are release-ordered before their
            // tickets -> visible now. Finalize + reset for next graph replay.
            const unsigned long long ls = ld_acq_u64(&g_lsum);
            const unsigned int       cn = ld_acq_u32(&g_cnt);
            const double Lsum = (double)(long long)ls * (1.0 / 4294967296.0);
            const double cnt  = (cn > 0u) ? (double)cn : 1.0;
            out[0] = (float)(Lsum / cnt);
            g_lsum = 0ull;
            g_cnt  = 0u;
            g_ctr  = 0u;
        }
    }
}

// ---------------------------------------------------------------------------
// Inputs (metadata order): inputs f32 [N,1000], target i32 [N],
//                          onehot_num, onehot_den, weights (unused)
// ---------------------------------------------------------------------------
extern "C" void kernel_launch(void* const* d_in, const int* in_sizes, int n_in,
                              void* d_out, int out_size)
{
    const float* inputs = (const float*)d_in[0];
    const int*   target = (const int*)d_in[1];
    float*       out    = (float*)d_out;

    const int N = in_sizes[1];
    const int nblk = (N + 7) / 8;            // 4096 for N=32768 (1 tok/warp)

    hll_fused<<<nblk, 256>>>(inputs, target, out, N, nblk);
}